// round 1
// baseline (speedup 1.0000x reference)
#include <cuda_runtime.h>

#define SLEN 1024
#define BSZ  64
#define DM   1024
#define NH   16
#define DK   64
#define MTOT (SLEN*BSZ)   // 65536

// Scratch (allocation-free rule: __device__ globals)
__device__ float g_q[(size_t)MTOT*DM];
__device__ float g_k[(size_t)MTOT*DM];
__device__ float g_v[(size_t)MTOT*DM];
__device__ float g_c[(size_t)MTOT*DM];

// ---------- packed fp32x2 helpers (Blackwell FFMA2 path) ----------
__device__ __forceinline__ unsigned long long pk2(float lo, float hi) {
    unsigned long long r;
    asm("mov.b64 %0, {%1, %2};" : "=l"(r) : "f"(lo), "f"(hi));
    return r;
}
__device__ __forceinline__ void upk2(float& lo, float& hi, unsigned long long v) {
    asm("mov.b64 {%0, %1}, %2;" : "=f"(lo), "=f"(hi) : "l"(v));
}
__device__ __forceinline__ unsigned long long ffma2(unsigned long long a,
                                                    unsigned long long b,
                                                    unsigned long long c) {
    unsigned long long d;
    asm("fma.rn.f32x2 %0, %1, %2, %3;" : "=l"(d) : "l"(a), "l"(b), "l"(c));
    return d;
}

// ---------- NT GEMM: C[M,N] = A[M,K] @ W[N,K]^T + bias ----------
// BM=BN=128, BK=16, 256 threads, 8x8 microtile per thread (as 8x4 f32x2 pairs)
__global__ __launch_bounds__(256)
void gemm_nt(const float* __restrict__ A, const float* __restrict__ W,
             const float* __restrict__ bias, float* __restrict__ C,
             int M, int N, int K) {
    __shared__ __align__(16) float As[16][132];
    __shared__ __align__(16) float Ws[16][132];

    const int tid = threadIdx.x;
    const int tx = tid & 15;        // 0..15 -> N microtile
    const int ty = tid >> 4;        // 0..15 -> M microtile
    const int m0 = blockIdx.y << 7;
    const int n0 = blockIdx.x << 7;

    const int lrow = tid >> 1;          // 0..127
    const int lcol = (tid & 1) << 3;    // 0 or 8
    const float* Ap = A + (size_t)(m0 + lrow) * K + lcol;
    const float* Wp = W + (size_t)(n0 + lrow) * K + lcol;

    unsigned long long acc[8][4];
#pragma unroll
    for (int i = 0; i < 8; i++)
#pragma unroll
        for (int j = 0; j < 4; j++) acc[i][j] = 0ULL;

    for (int k0 = 0; k0 < K; k0 += 16) {
        float4 a0 = *(const float4*)(Ap + k0);
        float4 a1 = *(const float4*)(Ap + k0 + 4);
        float4 w0 = *(const float4*)(Wp + k0);
        float4 w1 = *(const float4*)(Wp + k0 + 4);
        __syncthreads();
        As[lcol + 0][lrow] = a0.x; As[lcol + 1][lrow] = a0.y;
        As[lcol + 2][lrow] = a0.z; As[lcol + 3][lrow] = a0.w;
        As[lcol + 4][lrow] = a1.x; As[lcol + 5][lrow] = a1.y;
        As[lcol + 6][lrow] = a1.z; As[lcol + 7][lrow] = a1.w;
        Ws[lcol + 0][lrow] = w0.x; Ws[lcol + 1][lrow] = w0.y;
        Ws[lcol + 2][lrow] = w0.z; Ws[lcol + 3][lrow] = w0.w;
        Ws[lcol + 4][lrow] = w1.x; Ws[lcol + 5][lrow] = w1.y;
        Ws[lcol + 6][lrow] = w1.z; Ws[lcol + 7][lrow] = w1.w;
        __syncthreads();
#pragma unroll
        for (int kk = 0; kk < 16; kk++) {
            float4 afa = *(const float4*)&As[kk][ty << 3];
            float4 afb = *(const float4*)&As[kk][(ty << 3) + 4];
            float4 wfa = *(const float4*)&Ws[kk][tx << 3];
            float4 wfb = *(const float4*)&Ws[kk][(tx << 3) + 4];
            unsigned long long wp0 = pk2(wfa.x, wfa.y);
            unsigned long long wp1 = pk2(wfa.z, wfa.w);
            unsigned long long wp2 = pk2(wfb.x, wfb.y);
            unsigned long long wp3 = pk2(wfb.z, wfb.w);
            float af[8] = {afa.x, afa.y, afa.z, afa.w, afb.x, afb.y, afb.z, afb.w};
#pragma unroll
            for (int i = 0; i < 8; i++) {
                unsigned long long aa = pk2(af[i], af[i]);
                acc[i][0] = ffma2(aa, wp0, acc[i][0]);
                acc[i][1] = ffma2(aa, wp1, acc[i][1]);
                acc[i][2] = ffma2(aa, wp2, acc[i][2]);
                acc[i][3] = ffma2(aa, wp3, acc[i][3]);
            }
        }
    }

    float bv[8];
#pragma unroll
    for (int j = 0; j < 8; j++) bv[j] = bias[n0 + (tx << 3) + j];
#pragma unroll
    for (int i = 0; i < 8; i++) {
        float v[8];
#pragma unroll
        for (int jp = 0; jp < 4; jp++) upk2(v[2 * jp], v[2 * jp + 1], acc[i][jp]);
        float* cp = C + (size_t)(m0 + (ty << 3) + i) * N + n0 + (tx << 3);
        float4 r0 = make_float4(v[0] + bv[0], v[1] + bv[1], v[2] + bv[2], v[3] + bv[3]);
        float4 r1 = make_float4(v[4] + bv[4], v[5] + bv[5], v[6] + bv[6], v[7] + bv[7]);
        *(float4*)cp = r0;
        *(float4*)(cp + 4) = r1;
    }
}

// ---------- fused per-(s,h) attention ----------
// scores = Qh @ Kh^T / 8 (masked), A = scores @ Vh, softmax over d_k rows,
// written into concat layout [s, b, h*64+j].
__global__ __launch_bounds__(64)
void attn_kernel(const int* __restrict__ mask,
                 const float* __restrict__ Q, const float* __restrict__ K,
                 const float* __restrict__ V, float* __restrict__ Cc) {
    const int s = blockIdx.x;
    const int h = blockIdx.y;
    const int b = threadIdx.x;   // 0..63, one attention row per thread

    __shared__ float Kt[64][64];   // Kt[j][c] = K-head row c, dim j (reads broadcast)
    __shared__ float Vt[64][64];   // Vt[j][c]
    __shared__ float wred[2];

    const size_t rowbase = ((size_t)(s * 64 + b)) * DM + (size_t)h * 64;
    const float* kp = K + rowbase;
    const float* vp = V + rowbase;
#pragma unroll
    for (int j = 0; j < 64; j += 4) {
        float4 t = *(const float4*)(kp + j);
        Kt[j][b] = t.x; Kt[j + 1][b] = t.y; Kt[j + 2][b] = t.z; Kt[j + 3][b] = t.w;
        float4 u = *(const float4*)(vp + j);
        Vt[j][b] = u.x; Vt[j + 1][b] = u.y; Vt[j + 2][b] = u.z; Vt[j + 3][b] = u.w;
    }

    // mask_val[s] = sum_b mask[b][s]^2
    int mv = mask[b * SLEN + s];
    float msq = (float)(mv * mv);
#pragma unroll
    for (int off = 16; off; off >>= 1) msq += __shfl_xor_sync(0xffffffffu, msq, off);
    if ((b & 31) == 0) wred[b >> 5] = msq;

    float qr[64];
    const float* qp = Q + rowbase;
#pragma unroll
    for (int j = 0; j < 64; j += 4) {
        float4 t = *(const float4*)(qp + j);
        qr[j] = t.x; qr[j + 1] = t.y; qr[j + 2] = t.z; qr[j + 3] = t.w;
    }
    __syncthreads();
    const bool masked = (wred[0] + wred[1]) == 0.0f;

    float at[64];
#pragma unroll
    for (int j = 0; j < 64; j++) at[j] = 0.0f;

    for (int c = 0; c < 64; c++) {           // dynamic outer loop
        float sc = 0.0f;
#pragma unroll
        for (int j = 0; j < 64; j++) sc += qr[j] * Kt[j][c];
        sc = masked ? -1e9f : sc * 0.125f;
#pragma unroll
        for (int j = 0; j < 64; j++) at[j] += sc * Vt[j][c];
    }

    // softmax over d_k (the 64 at[] values), exact fp32
    float mx = at[0];
#pragma unroll
    for (int j = 1; j < 64; j++) mx = fmaxf(mx, at[j]);
    float sum = 0.0f;
#pragma unroll
    for (int j = 0; j < 64; j++) { at[j] = expf(at[j] - mx); sum += at[j]; }
    float inv = 1.0f / sum;

    float* op = Cc + rowbase;
#pragma unroll
    for (int j = 0; j < 64; j += 4) {
        float4 t = make_float4(at[j] * inv, at[j + 1] * inv, at[j + 2] * inv, at[j + 3] * inv);
        *(float4*)(op + j) = t;
    }
}

extern "C" void kernel_launch(void* const* d_in, const int* in_sizes, int n_in,
                              void* d_out, int out_size) {
    const float* kin  = (const float*)d_in[0];
    const float* vin  = (const float*)d_in[1];
    const int*   mask = (const int*)  d_in[2];
    const float* gt   = (const float*)d_in[3];
    const float* Wq   = (const float*)d_in[4];
    const float* bq   = (const float*)d_in[5];
    const float* Wk   = (const float*)d_in[6];
    const float* bk   = (const float*)d_in[7];
    const float* Wv   = (const float*)d_in[8];
    const float* bv   = (const float*)d_in[9];
    const float* Wo   = (const float*)d_in[10];
    const float* bo   = (const float*)d_in[11];
    float* out = (float*)d_out;

    float *pq, *pk, *pv, *pc;
    cudaGetSymbolAddress((void**)&pq, g_q);
    cudaGetSymbolAddress((void**)&pk, g_k);
    cudaGetSymbolAddress((void**)&pv, g_v);
    cudaGetSymbolAddress((void**)&pc, g_c);

    dim3 gg(DM / 128, MTOT / 128);
    dim3 bb(256);
    gemm_nt<<<gg, bb>>>(gt,  Wq, bq, pq, MTOT, DM, DM);
    gemm_nt<<<gg, bb>>>(kin, Wk, bk, pk, MTOT, DM, DM);
    gemm_nt<<<gg, bb>>>(vin, Wv, bv, pv, MTOT, DM, DM);
    attn_kernel<<<dim3(SLEN, NH), 64>>>(mask, pq, pk, pv, pc);
    gemm_nt<<<gg, bb>>>(pc, Wo, bo, out, MTOT, DM, DM);
}

// round 3
// speedup vs baseline: 3.6893x; 3.6893x over previous
#include <cuda_runtime.h>
#include <cuda_bf16.h>
#include <cstdint>

#define SLEN 1024
#define BSZ  64
#define DM   1024
#define NH   16
#define DK   64
#define MTOT (SLEN*BSZ)   // 65536

// GEMM tiling (warp-level HMMA; tcgen05 PTX not accepted by this toolchain's
// compute_103 target)
#define BM 128
#define BN 128
#define BK 32
#define NSTAGES (DM/BK)        // 32
#define GEMM_THREADS 256

// smem: per stage 4 tiles (Ah, Al, Wh, Wl), each 128 rows x 32 bf16 (64B rows,
// XOR-8-chunk swizzle) = 8KB. Stage = 32KB, double buffered = 64KB dynamic.
#define TILE_BYTES 8192
#define STAGE_BYTES 32768
#define AH_OFF 0
#define AL_OFF 8192
#define WH_OFF 16384
#define WL_OFF 24576
#define SMEM_TOTAL (2*STAGE_BYTES)

// Scratch (allocation-free rule: __device__ globals)
__device__ float g_q[(size_t)MTOT*DM];
__device__ float g_k[(size_t)MTOT*DM];
__device__ float g_v[(size_t)MTOT*DM];
__device__ float g_c[(size_t)MTOT*DM];

// swizzled byte offset inside one tile: row-major 64B rows, 8B chunks XORed by row
__device__ __forceinline__ uint32_t swz(uint32_t row, uint32_t col_elem) {
    uint32_t chunk = (col_elem >> 2) ^ (row & 7);
    return row * 64 + chunk * 8 + (col_elem & 3) * 2;
}

// truncation split: x -> hi(bf16, truncated) + lo(bf16 rn of residual)
__device__ __forceinline__ void split2(float x, float y, uint32_t& hi2, uint32_t& lo2) {
    uint32_t xb = __float_as_uint(x), yb = __float_as_uint(y);
    hi2 = __byte_perm(xb, yb, 0x7632);        // bf16x2 {hi(x), hi(y)}
    float xr = x - __uint_as_float(xb & 0xFFFF0000u);
    float yr = y - __uint_as_float(yb & 0xFFFF0000u);
    __nv_bfloat162 l = __floats2bfloat162_rn(xr, yr);
    lo2 = *reinterpret_cast<uint32_t*>(&l);
}

__device__ __forceinline__ void mma_bf16(float* d, const uint32_t* a, const uint32_t* b) {
    asm volatile(
        "mma.sync.aligned.m16n8k16.row.col.f32.bf16.bf16.f32 "
        "{%0,%1,%2,%3}, {%4,%5,%6,%7}, {%8,%9}, {%0,%1,%2,%3};"
        : "+f"(d[0]), "+f"(d[1]), "+f"(d[2]), "+f"(d[3])
        : "r"(a[0]), "r"(a[1]), "r"(a[2]), "r"(a[3]), "r"(b[0]), "r"(b[1]));
}

// ---------- split-bf16 3-pass HMMA GEMM: C[M,N] = A[M,K] @ W[N,K]^T + bias ----------
__global__ __launch_bounds__(GEMM_THREADS, 1)
void gemm_tc(const float* __restrict__ A, const float* __restrict__ W,
             const float* __restrict__ bias, float* __restrict__ C) {
    extern __shared__ char smem[];
    const int tid = threadIdx.x;
    const int lane = tid & 31;
    const int wid = tid >> 5;
    const int wm = wid & 1;         // 2 warp rows
    const int wn = wid >> 1;        // 4 warp cols
    const int g = lane >> 2;        // 0..7
    const int c = lane & 3;         // 0..3
    const int m0 = blockIdx.y * BM;
    const int n0 = blockIdx.x * BN;

    // per-thread global load mapping: 4 rows each for A and W, col chunk c4
    const int c4 = tid & 7;
    const int rbase = tid >> 3;     // 0..31
    const float* pA[4];
    const float* pW[4];
#pragma unroll
    for (int i = 0; i < 4; i++) {
        pA[i] = A + (size_t)(m0 + rbase + i * 32) * DM + c4 * 4;
        pW[i] = W + (size_t)(n0 + rbase + i * 32) * DM + c4 * 4;
    }
    const uint32_t soff = (rbase) * 64;   // row part added per i below

    float acc[4][4][4];
#pragma unroll
    for (int mf = 0; mf < 4; mf++)
#pragma unroll
        for (int nf = 0; nf < 4; nf++)
#pragma unroll
            for (int q = 0; q < 4; q++) acc[mf][nf][q] = 0.0f;

    float4 va[4], vw[4];
#pragma unroll
    for (int i = 0; i < 4; i++) { va[i] = *(const float4*)(pA[i]); vw[i] = *(const float4*)(pW[i]); }

    // store stage 0
    {
        char* sb = smem;
#pragma unroll
        for (int i = 0; i < 4; i++) {
            uint32_t row = rbase + i * 32;
            uint32_t off = row * 64 + ((uint32_t)(c4 ^ (row & 7))) * 8;
            uint32_t h0, l0, h1, l1;
            split2(va[i].x, va[i].y, h0, l0); split2(va[i].z, va[i].w, h1, l1);
            *(uint2*)(sb + AH_OFF + off) = make_uint2(h0, h1);
            *(uint2*)(sb + AL_OFF + off) = make_uint2(l0, l1);
            split2(vw[i].x, vw[i].y, h0, l0); split2(vw[i].z, vw[i].w, h1, l1);
            *(uint2*)(sb + WH_OFF + off) = make_uint2(h0, h1);
            *(uint2*)(sb + WL_OFF + off) = make_uint2(l0, l1);
        }
    }
    __syncthreads();

#pragma unroll 1
    for (int s = 0; s < NSTAGES; s++) {
        // prefetch next stage into regs
        if (s + 1 < NSTAGES) {
            const int k0 = (s + 1) * BK;
#pragma unroll
            for (int i = 0; i < 4; i++) { va[i] = *(const float4*)(pA[i] + k0); vw[i] = *(const float4*)(pW[i] + k0); }
        }

        // compute from buffer s&1
        {
            char* sb = smem + (s & 1) * STAGE_BYTES;
            char* pAh = sb + AH_OFF; char* pAl = sb + AL_OFF;
            char* pWh = sb + WH_OFF; char* pWl = sb + WL_OFF;
#pragma unroll
            for (int kk = 0; kk < 2; kk++) {
                uint32_t ah[4][4], al[4][4], bh[4][2], bl[4][2];
                const int colk = kk * 16 + c * 2;
#pragma unroll
                for (int mf = 0; mf < 4; mf++) {
                    const uint32_t r0 = wm * 64 + mf * 16 + g;
                    ah[mf][0] = *(const uint32_t*)(pAh + swz(r0,     colk));
                    ah[mf][1] = *(const uint32_t*)(pAh + swz(r0 + 8, colk));
                    ah[mf][2] = *(const uint32_t*)(pAh + swz(r0,     colk + 8));
                    ah[mf][3] = *(const uint32_t*)(pAh + swz(r0 + 8, colk + 8));
                    al[mf][0] = *(const uint32_t*)(pAl + swz(r0,     colk));
                    al[mf][1] = *(const uint32_t*)(pAl + swz(r0 + 8, colk));
                    al[mf][2] = *(const uint32_t*)(pAl + swz(r0,     colk + 8));
                    al[mf][3] = *(const uint32_t*)(pAl + swz(r0 + 8, colk + 8));
                }
#pragma unroll
                for (int nf = 0; nf < 4; nf++) {
                    const uint32_t rn = wn * 32 + nf * 8 + g;
                    bh[nf][0] = *(const uint32_t*)(pWh + swz(rn, colk));
                    bh[nf][1] = *(const uint32_t*)(pWh + swz(rn, colk + 8));
                    bl[nf][0] = *(const uint32_t*)(pWl + swz(rn, colk));
                    bl[nf][1] = *(const uint32_t*)(pWl + swz(rn, colk + 8));
                }
#pragma unroll
                for (int mf = 0; mf < 4; mf++)
#pragma unroll
                    for (int nf = 0; nf < 4; nf++) {
                        mma_bf16(acc[mf][nf], ah[mf], bh[nf]);
                        mma_bf16(acc[mf][nf], ah[mf], bl[nf]);
                        mma_bf16(acc[mf][nf], al[mf], bh[nf]);
                    }
            }
        }

        // store next stage (writes buffer last read two iterations ago — safe)
        if (s + 1 < NSTAGES) {
            char* sb = smem + ((s + 1) & 1) * STAGE_BYTES;
#pragma unroll
            for (int i = 0; i < 4; i++) {
                uint32_t row = rbase + i * 32;
                uint32_t off = row * 64 + ((uint32_t)(c4 ^ (row & 7))) * 8;
                uint32_t h0, l0, h1, l1;
                split2(va[i].x, va[i].y, h0, l0); split2(va[i].z, va[i].w, h1, l1);
                *(uint2*)(sb + AH_OFF + off) = make_uint2(h0, h1);
                *(uint2*)(sb + AL_OFF + off) = make_uint2(l0, l1);
                split2(vw[i].x, vw[i].y, h0, l0); split2(vw[i].z, vw[i].w, h1, l1);
                *(uint2*)(sb + WH_OFF + off) = make_uint2(h0, h1);
                *(uint2*)(sb + WL_OFF + off) = make_uint2(l0, l1);
            }
        }
        __syncthreads();
    }

    // epilogue
    float2 bvv[4];
#pragma unroll
    for (int nf = 0; nf < 4; nf++) {
        int col = n0 + wn * 32 + nf * 8 + c * 2;
        bvv[nf] = make_float2(bias[col], bias[col + 1]);
    }
#pragma unroll
    for (int mf = 0; mf < 4; mf++) {
        const int row = m0 + wm * 64 + mf * 16 + g;
#pragma unroll
        for (int nf = 0; nf < 4; nf++) {
            const int col = n0 + wn * 32 + nf * 8 + c * 2;
            float2 v0 = make_float2(acc[mf][nf][0] + bvv[nf].x, acc[mf][nf][1] + bvv[nf].y);
            float2 v1 = make_float2(acc[mf][nf][2] + bvv[nf].x, acc[mf][nf][3] + bvv[nf].y);
            *(float2*)(C + (size_t)row * DM + col) = v0;
            *(float2*)(C + (size_t)(row + 8) * DM + col) = v1;
        }
    }
}

// ---------- fused per-(s,h) attention (unchanged from passing R0) ----------
__global__ __launch_bounds__(64)
void attn_kernel(const int* __restrict__ mask,
                 const float* __restrict__ Q, const float* __restrict__ K,
                 const float* __restrict__ V, float* __restrict__ Cc) {
    const int s = blockIdx.x;
    const int h = blockIdx.y;
    const int b = threadIdx.x;

    __shared__ float Kt[64][64];
    __shared__ float Vt[64][64];
    __shared__ float wred[2];

    const size_t rowbase = ((size_t)(s * 64 + b)) * DM + (size_t)h * 64;
    const float* kp = K + rowbase;
    const float* vp = V + rowbase;
#pragma unroll
    for (int j = 0; j < 64; j += 4) {
        float4 t = *(const float4*)(kp + j);
        Kt[j][b] = t.x; Kt[j + 1][b] = t.y; Kt[j + 2][b] = t.z; Kt[j + 3][b] = t.w;
        float4 u = *(const float4*)(vp + j);
        Vt[j][b] = u.x; Vt[j + 1][b] = u.y; Vt[j + 2][b] = u.z; Vt[j + 3][b] = u.w;
    }

    int mv = mask[b * SLEN + s];
    float msq = (float)(mv * mv);
#pragma unroll
    for (int off = 16; off; off >>= 1) msq += __shfl_xor_sync(0xffffffffu, msq, off);
    if ((b & 31) == 0) wred[b >> 5] = msq;

    float qr[64];
    const float* qp = Q + rowbase;
#pragma unroll
    for (int j = 0; j < 64; j += 4) {
        float4 t = *(const float4*)(qp + j);
        qr[j] = t.x; qr[j + 1] = t.y; qr[j + 2] = t.z; qr[j + 3] = t.w;
    }
    __syncthreads();
    const bool masked = (wred[0] + wred[1]) == 0.0f;

    float at[64];
#pragma unroll
    for (int j = 0; j < 64; j++) at[j] = 0.0f;

    for (int cc = 0; cc < 64; cc++) {
        float sc = 0.0f;
#pragma unroll
        for (int j = 0; j < 64; j++) sc += qr[j] * Kt[j][cc];
        sc = masked ? -1e9f : sc * 0.125f;
#pragma unroll
        for (int j = 0; j < 64; j++) at[j] += sc * Vt[j][cc];
    }

    float mx = at[0];
#pragma unroll
    for (int j = 1; j < 64; j++) mx = fmaxf(mx, at[j]);
    float sum = 0.0f;
#pragma unroll
    for (int j = 0; j < 64; j++) { at[j] = expf(at[j] - mx); sum += at[j]; }
    float inv = 1.0f / sum;

    float* op = Cc + rowbase;
#pragma unroll
    for (int j = 0; j < 64; j += 4) {
        float4 t = make_float4(at[j] * inv, at[j + 1] * inv, at[j + 2] * inv, at[j + 3] * inv);
        *(float4*)(op + j) = t;
    }
}

extern "C" void kernel_launch(void* const* d_in, const int* in_sizes, int n_in,
                              void* d_out, int out_size) {
    const float* kin  = (const float*)d_in[0];
    const float* vin  = (const float*)d_in[1];
    const int*   mask = (const int*)  d_in[2];
    const float* gt   = (const float*)d_in[3];
    const float* Wq   = (const float*)d_in[4];
    const float* bq   = (const float*)d_in[5];
    const float* Wk   = (const float*)d_in[6];
    const float* bk   = (const float*)d_in[7];
    const float* Wv   = (const float*)d_in[8];
    const float* bv   = (const float*)d_in[9];
    const float* Wo   = (const float*)d_in[10];
    const float* bo   = (const float*)d_in[11];
    float* out = (float*)d_out;

    float *pq, *pk, *pv, *pc;
    cudaGetSymbolAddress((void**)&pq, g_q);
    cudaGetSymbolAddress((void**)&pk, g_k);
    cudaGetSymbolAddress((void**)&pv, g_v);
    cudaGetSymbolAddress((void**)&pc, g_c);

    cudaFuncSetAttribute(gemm_tc, cudaFuncAttributeMaxDynamicSharedMemorySize, SMEM_TOTAL);

    dim3 gg(DM / BN, MTOT / BM);   // (8, 512): n-fastest => A tiles reused via L2
    gemm_tc<<<gg, GEMM_THREADS, SMEM_TOTAL>>>(gt,  Wq, bq, pq);
    gemm_tc<<<gg, GEMM_THREADS, SMEM_TOTAL>>>(kin, Wk, bk, pk);
    gemm_tc<<<gg, GEMM_THREADS, SMEM_TOTAL>>>(vin, Wv, bv, pv);
    attn_kernel<<<dim3(SLEN, NH), 64>>>(mask, pq, pk, pv, pc);
    gemm_tc<<<gg, GEMM_THREADS, SMEM_TOTAL>>>(pc, Wo, bo, out);
}

// round 8
// speedup vs baseline: 4.1708x; 1.1305x over previous
#include <cuda_runtime.h>
#include <cuda_bf16.h>
#include <cstdint>

#define SLEN 1024
#define BSZ  64
#define DM   1024
#define NH   16
#define DK   64
#define MTOT (SLEN*BSZ)   // 65536

// GEMM tiling (warp-level HMMA; tcgen05 PTX not accepted by this toolchain's
// compute_103 target)
#define BM 128
#define BN 128
#define BK 32
#define NSTAGES (DM/BK)        // 32
#define GEMM_THREADS 256

#define TILE_BYTES 8192
#define STAGE_BYTES 32768
#define AH_OFF 0
#define AL_OFF 8192
#define WH_OFF 16384
#define WL_OFF 24576
#define SMEM_TOTAL (2*STAGE_BYTES)

// Scratch (allocation-free rule: __device__ globals)
__device__ float g_q[(size_t)MTOT*DM];
__device__ float g_k[(size_t)MTOT*DM];
__device__ float g_v[(size_t)MTOT*DM];
__device__ float g_c[(size_t)MTOT*DM];

typedef unsigned long long ull;

// ---------- packed fp32x2 helpers ----------
__device__ __forceinline__ ull pk2(float lo, float hi) {
    ull r;
    asm("mov.b64 %0, {%1, %2};" : "=l"(r) : "f"(lo), "f"(hi));
    return r;
}
__device__ __forceinline__ void upk2(float& lo, float& hi, ull v) {
    asm("mov.b64 {%0, %1}, %2;" : "=f"(lo), "=f"(hi) : "l"(v));
}
__device__ __forceinline__ ull ffma2(ull a, ull b, ull c) {
    ull d;
    asm("fma.rn.f32x2 %0, %1, %2, %3;" : "=l"(d) : "l"(a), "l"(b), "l"(c));
    return d;
}

// swizzled byte offset inside one GEMM tile: 64B rows, 8B chunks XORed by row
__device__ __forceinline__ uint32_t swz(uint32_t row, uint32_t col_elem) {
    uint32_t chunk = (col_elem >> 2) ^ (row & 7);
    return row * 64 + chunk * 8 + (col_elem & 3) * 2;
}

// truncation split: x -> hi(bf16, truncated) + lo(bf16 rn of residual)
__device__ __forceinline__ void split2(float x, float y, uint32_t& hi2, uint32_t& lo2) {
    uint32_t xb = __float_as_uint(x), yb = __float_as_uint(y);
    hi2 = __byte_perm(xb, yb, 0x7632);
    float xr = x - __uint_as_float(xb & 0xFFFF0000u);
    float yr = y - __uint_as_float(yb & 0xFFFF0000u);
    __nv_bfloat162 l = __floats2bfloat162_rn(xr, yr);
    lo2 = *reinterpret_cast<uint32_t*>(&l);
}

__device__ __forceinline__ void mma_bf16(float* d, const uint32_t* a, const uint32_t* b) {
    asm volatile(
        "mma.sync.aligned.m16n8k16.row.col.f32.bf16.bf16.f32 "
        "{%0,%1,%2,%3}, {%4,%5,%6,%7}, {%8,%9}, {%0,%1,%2,%3};"
        : "+f"(d[0]), "+f"(d[1]), "+f"(d[2]), "+f"(d[3])
        : "r"(a[0]), "r"(a[1]), "r"(a[2]), "r"(a[3]), "r"(b[0]), "r"(b[1]));
}

// ---------- split-bf16 3-pass HMMA GEMM (unchanged from R2 win) ----------
__global__ __launch_bounds__(GEMM_THREADS, 1)
void gemm_tc(const float* __restrict__ A, const float* __restrict__ W,
             const float* __restrict__ bias, float* __restrict__ C) {
    extern __shared__ char smem[];
    const int tid = threadIdx.x;
    const int lane = tid & 31;
    const int wid = tid >> 5;
    const int wm = wid & 1;
    const int wn = wid >> 1;
    const int g = lane >> 2;
    const int c = lane & 3;
    const int m0 = blockIdx.y * BM;
    const int n0 = blockIdx.x * BN;

    const int c4 = tid & 7;
    const int rbase = tid >> 3;
    const float* pA[4];
    const float* pW[4];
#pragma unroll
    for (int i = 0; i < 4; i++) {
        pA[i] = A + (size_t)(m0 + rbase + i * 32) * DM + c4 * 4;
        pW[i] = W + (size_t)(n0 + rbase + i * 32) * DM + c4 * 4;
    }

    float acc[4][4][4];
#pragma unroll
    for (int mf = 0; mf < 4; mf++)
#pragma unroll
        for (int nf = 0; nf < 4; nf++)
#pragma unroll
            for (int q = 0; q < 4; q++) acc[mf][nf][q] = 0.0f;

    float4 va[4], vw[4];
#pragma unroll
    for (int i = 0; i < 4; i++) { va[i] = *(const float4*)(pA[i]); vw[i] = *(const float4*)(pW[i]); }

    {
        char* sb = smem;
#pragma unroll
        for (int i = 0; i < 4; i++) {
            uint32_t row = rbase + i * 32;
            uint32_t off = row * 64 + ((uint32_t)(c4 ^ (row & 7))) * 8;
            uint32_t h0, l0, h1, l1;
            split2(va[i].x, va[i].y, h0, l0); split2(va[i].z, va[i].w, h1, l1);
            *(uint2*)(sb + AH_OFF + off) = make_uint2(h0, h1);
            *(uint2*)(sb + AL_OFF + off) = make_uint2(l0, l1);
            split2(vw[i].x, vw[i].y, h0, l0); split2(vw[i].z, vw[i].w, h1, l1);
            *(uint2*)(sb + WH_OFF + off) = make_uint2(h0, h1);
            *(uint2*)(sb + WL_OFF + off) = make_uint2(l0, l1);
        }
    }
    __syncthreads();

#pragma unroll 1
    for (int s = 0; s < NSTAGES; s++) {
        if (s + 1 < NSTAGES) {
            const int k0 = (s + 1) * BK;
#pragma unroll
            for (int i = 0; i < 4; i++) { va[i] = *(const float4*)(pA[i] + k0); vw[i] = *(const float4*)(pW[i] + k0); }
        }

        {
            char* sb = smem + (s & 1) * STAGE_BYTES;
            char* pAh = sb + AH_OFF; char* pAl = sb + AL_OFF;
            char* pWh = sb + WH_OFF; char* pWl = sb + WL_OFF;
#pragma unroll
            for (int kk = 0; kk < 2; kk++) {
                uint32_t ah[4][4], al[4][4], bh[4][2], bl[4][2];
                const int colk = kk * 16 + c * 2;
#pragma unroll
                for (int mf = 0; mf < 4; mf++) {
                    const uint32_t r0 = wm * 64 + mf * 16 + g;
                    ah[mf][0] = *(const uint32_t*)(pAh + swz(r0,     colk));
                    ah[mf][1] = *(const uint32_t*)(pAh + swz(r0 + 8, colk));
                    ah[mf][2] = *(const uint32_t*)(pAh + swz(r0,     colk + 8));
                    ah[mf][3] = *(const uint32_t*)(pAh + swz(r0 + 8, colk + 8));
                    al[mf][0] = *(const uint32_t*)(pAl + swz(r0,     colk));
                    al[mf][1] = *(const uint32_t*)(pAl + swz(r0 + 8, colk));
                    al[mf][2] = *(const uint32_t*)(pAl + swz(r0,     colk + 8));
                    al[mf][3] = *(const uint32_t*)(pAl + swz(r0 + 8, colk + 8));
                }
#pragma unroll
                for (int nf = 0; nf < 4; nf++) {
                    const uint32_t rn = wn * 32 + nf * 8 + g;
                    bh[nf][0] = *(const uint32_t*)(pWh + swz(rn, colk));
                    bh[nf][1] = *(const uint32_t*)(pWh + swz(rn, colk + 8));
                    bl[nf][0] = *(const uint32_t*)(pWl + swz(rn, colk));
                    bl[nf][1] = *(const uint32_t*)(pWl + swz(rn, colk + 8));
                }
#pragma unroll
                for (int mf = 0; mf < 4; mf++)
#pragma unroll
                    for (int nf = 0; nf < 4; nf++) {
                        mma_bf16(acc[mf][nf], ah[mf], bh[nf]);
                        mma_bf16(acc[mf][nf], ah[mf], bl[nf]);
                        mma_bf16(acc[mf][nf], al[mf], bh[nf]);
                    }
            }
        }

        if (s + 1 < NSTAGES) {
            char* sb = smem + ((s + 1) & 1) * STAGE_BYTES;
#pragma unroll
            for (int i = 0; i < 4; i++) {
                uint32_t row = rbase + i * 32;
                uint32_t off = row * 64 + ((uint32_t)(c4 ^ (row & 7))) * 8;
                uint32_t h0, l0, h1, l1;
                split2(va[i].x, va[i].y, h0, l0); split2(va[i].z, va[i].w, h1, l1);
                *(uint2*)(sb + AH_OFF + off) = make_uint2(h0, h1);
                *(uint2*)(sb + AL_OFF + off) = make_uint2(l0, l1);
                split2(vw[i].x, vw[i].y, h0, l0); split2(vw[i].z, vw[i].w, h1, l1);
                *(uint2*)(sb + WH_OFF + off) = make_uint2(h0, h1);
                *(uint2*)(sb + WL_OFF + off) = make_uint2(l0, l1);
            }
        }
        __syncthreads();
    }

    float2 bvv[4];
#pragma unroll
    for (int nf = 0; nf < 4; nf++) {
        int col = n0 + wn * 32 + nf * 8 + c * 2;
        bvv[nf] = make_float2(bias[col], bias[col + 1]);
    }
#pragma unroll
    for (int mf = 0; mf < 4; mf++) {
        const int row = m0 + wm * 64 + mf * 16 + g;
#pragma unroll
        for (int nf = 0; nf < 4; nf++) {
            const int col = n0 + wn * 32 + nf * 8 + c * 2;
            float2 v0 = make_float2(acc[mf][nf][0] + bvv[nf].x, acc[mf][nf][1] + bvv[nf].y);
            float2 v1 = make_float2(acc[mf][nf][2] + bvv[nf].x, acc[mf][nf][3] + bvv[nf].y);
            *(float2*)(C + (size_t)row * DM + col) = v0;
            *(float2*)(C + (size_t)(row + 8) * DM + col) = v1;
        }
    }
}

// ---------- attention v2.1: coalesced, f32x2, j-split across lane pairs ----------
// Block = (s,h), 128 threads. Thread t: b = t>>1, half = t&1.
// j-sets interleaved in 16-blocks: half0: [0,16)u[32,48); half1: [16,32)u[48,64)
// smem (floats): Ks[64][64] @0, Vs[64][64] @4096, Qs[64][66] @8192, St[64][68] @12416
// (Qs stride 66 -> 264B rows: float2 stores stay 8B-aligned for every row;
//  the misaligned-address fault of v2 was Qs stride 65 = 260B.)
#define KS_OFF 0
#define VS_OFF 4096
#define QS_OFF 8192
#define QS_STRIDE 66
#define ST_OFF (QS_OFF + 64*QS_STRIDE)          // 12416
#define ATTN_SMEM_FLOATS (ST_OFF + 64*68)       // 16768 floats = 67072 bytes

__global__ __launch_bounds__(128)
void attn_kernel(const int* __restrict__ mask,
                 const float* __restrict__ Q, const float* __restrict__ K,
                 const float* __restrict__ V, float* __restrict__ Cc) {
    extern __shared__ float sm[];
    float* Ks = sm + KS_OFF;   // [c][j], stride 64
    float* Vs = sm + VS_OFF;   // [c][j], stride 64
    float* Qs = sm + QS_OFF;   // [b][j], stride 66
    float* St = sm + ST_OFF;   // [b][j], stride 68
    __shared__ float wred[2];

    const int s = blockIdx.x;
    const int h = blockIdx.y;
    const int tid = threadIdx.x;
    const int lane = tid & 31;
    const int w = tid >> 5;

    const size_t head_base = ((size_t)s * 64) * DM + (size_t)h * 64;

    // coalesced loads: warp w handles rows [w*16, w*16+16)
#pragma unroll 4
    for (int i = 0; i < 16; i++) {
        const int row = w * 16 + i;
        const float* gsrc = K + head_base + (size_t)row * DM + lane * 2;
        *(float2*)&Ks[row * 64 + lane * 2] = *(const float2*)gsrc;
        gsrc = V + head_base + (size_t)row * DM + lane * 2;
        *(float2*)&Vs[row * 64 + lane * 2] = *(const float2*)gsrc;
        gsrc = Q + head_base + (size_t)row * DM + lane * 2;
        *(float2*)&Qs[row * QS_STRIDE + lane * 2] = *(const float2*)gsrc;
    }

    if (tid < 64) {
        int mv = mask[tid * SLEN + s];
        float m = (float)(mv * mv);
#pragma unroll
        for (int off = 16; off; off >>= 1) m += __shfl_xor_sync(0xffffffffu, m, off);
        if (lane == 0) wred[w] = m;
    }
    __syncthreads();
    const bool masked = (wred[0] + wred[1]) == 0.0f;

    const int b = tid >> 1;
    const int half = tid & 1;
    const int jb0 = half * 16;
    const int jb1 = 32 + half * 16;

    // load this thread's q slice (one-time scalar LDS, <=2-way conflicts)
    ull qr2[16];
#pragma unroll
    for (int i = 0; i < 8; i++) {
        qr2[i]     = pk2(Qs[b * QS_STRIDE + jb0 + 2 * i], Qs[b * QS_STRIDE + jb0 + 2 * i + 1]);
        qr2[8 + i] = pk2(Qs[b * QS_STRIDE + jb1 + 2 * i], Qs[b * QS_STRIDE + jb1 + 2 * i + 1]);
    }

    ull at2[16];
#pragma unroll
    for (int i = 0; i < 16; i++) at2[i] = 0ULL;

#pragma unroll 1
    for (int cg = 0; cg < 8; cg++) {
        ull sc2[8];
#pragma unroll
        for (int i = 0; i < 8; i++) sc2[i] = 0ULL;
#pragma unroll
        for (int cc = 0; cc < 8; cc++) {
            const int c = cg * 8 + cc;
            const ulonglong2* kp0 = (const ulonglong2*)&Ks[c * 64 + jb0];
            const ulonglong2* kp1 = (const ulonglong2*)&Ks[c * 64 + jb1];
#pragma unroll
            for (int i = 0; i < 4; i++) {
                ulonglong2 k4 = kp0[i];
                sc2[cc] = ffma2(qr2[2 * i], k4.x, sc2[cc]);
                sc2[cc] = ffma2(qr2[2 * i + 1], k4.y, sc2[cc]);
                ulonglong2 k5 = kp1[i];
                sc2[cc] = ffma2(qr2[8 + 2 * i], k5.x, sc2[cc]);
                sc2[cc] = ffma2(qr2[8 + 2 * i + 1], k5.y, sc2[cc]);
            }
        }
        float sc[8];
#pragma unroll
        for (int cc = 0; cc < 8; cc++) {
            float lo, hi;
            upk2(lo, hi, sc2[cc]);
            float sv = lo + hi;
            sv += __shfl_xor_sync(0xffffffffu, sv, 1);   // partner half of the dot
            sc[cc] = masked ? -1e9f : sv * 0.125f;
        }
#pragma unroll
        for (int cc = 0; cc < 8; cc++) {
            const int c = cg * 8 + cc;
            const ull sb2 = pk2(sc[cc], sc[cc]);
            const ulonglong2* vp0 = (const ulonglong2*)&Vs[c * 64 + jb0];
            const ulonglong2* vp1 = (const ulonglong2*)&Vs[c * 64 + jb1];
#pragma unroll
            for (int i = 0; i < 4; i++) {
                ulonglong2 v4 = vp0[i];
                at2[2 * i]     = ffma2(sb2, v4.x, at2[2 * i]);
                at2[2 * i + 1] = ffma2(sb2, v4.y, at2[2 * i + 1]);
                ulonglong2 v5 = vp1[i];
                at2[8 + 2 * i]     = ffma2(sb2, v5.x, at2[8 + 2 * i]);
                at2[8 + 2 * i + 1] = ffma2(sb2, v5.y, at2[8 + 2 * i + 1]);
            }
        }
    }

    // softmax over d_k (all 64 j, split across lane pair)
    float e[32];
    float mx = -3.4e38f;
#pragma unroll
    for (int i = 0; i < 16; i++) {
        float lo, hi;
        upk2(lo, hi, at2[i]);
        e[2 * i] = lo; e[2 * i + 1] = hi;
        mx = fmaxf(mx, fmaxf(lo, hi));
    }
    mx = fmaxf(mx, __shfl_xor_sync(0xffffffffu, mx, 1));
    float sum = 0.0f;
#pragma unroll
    for (int i = 0; i < 32; i++) { e[i] = __expf(e[i] - mx); sum += e[i]; }
    sum += __shfl_xor_sync(0xffffffffu, sum, 1);
    const float inv = 1.0f / sum;

    // stage to smem (stride 68 = 272B: float4 slots stay 16B-aligned)
#pragma unroll
    for (int i = 0; i < 4; i++) {
        float4 t0 = make_float4(e[4 * i] * inv, e[4 * i + 1] * inv,
                                e[4 * i + 2] * inv, e[4 * i + 3] * inv);
        *(float4*)&St[b * 68 + jb0 + 4 * i] = t0;
        float4 t1 = make_float4(e[16 + 4 * i] * inv, e[16 + 4 * i + 1] * inv,
                                e[16 + 4 * i + 2] * inv, e[16 + 4 * i + 3] * inv);
        *(float4*)&St[b * 68 + jb1 + 4 * i] = t1;
    }
    __syncthreads();

#pragma unroll 4
    for (int i = 0; i < 16; i++) {
        const int row = w * 16 + i;
        float2 t = *(const float2*)&St[row * 68 + lane * 2];
        *(float2*)(Cc + head_base + (size_t)row * DM + lane * 2) = t;
    }
}

extern "C" void kernel_launch(void* const* d_in, const int* in_sizes, int n_in,
                              void* d_out, int out_size) {
    const float* kin  = (const float*)d_in[0];
    const float* vin  = (const float*)d_in[1];
    const int*   mask = (const int*)  d_in[2];
    const float* gt   = (const float*)d_in[3];
    const float* Wq   = (const float*)d_in[4];
    const float* bq   = (const float*)d_in[5];
    const float* Wk   = (const float*)d_in[6];
    const float* bk   = (const float*)d_in[7];
    const float* Wv   = (const float*)d_in[8];
    const float* bv   = (const float*)d_in[9];
    const float* Wo   = (const float*)d_in[10];
    const float* bo   = (const float*)d_in[11];
    float* out = (float*)d_out;

    float *pq, *pk, *pv, *pc;
    cudaGetSymbolAddress((void**)&pq, g_q);
    cudaGetSymbolAddress((void**)&pk, g_k);
    cudaGetSymbolAddress((void**)&pv, g_v);
    cudaGetSymbolAddress((void**)&pc, g_c);

    cudaFuncSetAttribute(gemm_tc, cudaFuncAttributeMaxDynamicSharedMemorySize, SMEM_TOTAL);
    cudaFuncSetAttribute(attn_kernel, cudaFuncAttributeMaxDynamicSharedMemorySize,
                         ATTN_SMEM_FLOATS * 4);

    dim3 gg(DM / BN, MTOT / BM);
    gemm_tc<<<gg, GEMM_THREADS, SMEM_TOTAL>>>(gt,  Wq, bq, pq);
    gemm_tc<<<gg, GEMM_THREADS, SMEM_TOTAL>>>(kin, Wk, bk, pk);
    gemm_tc<<<gg, GEMM_THREADS, SMEM_TOTAL>>>(vin, Wv, bv, pv);
    attn_kernel<<<dim3(SLEN, NH), 128, ATTN_SMEM_FLOATS * 4>>>(mask, pq, pk, pv, pc);
    gemm_tc<<<gg, GEMM_THREADS, SMEM_TOTAL>>>(pc, Wo, bo, out);
}